// round 3
// baseline (speedup 1.0000x reference)
#include <cuda_runtime.h>

#define TB  576
#define BT  4

__device__ __forceinline__ float sigf(float x){
    return __fdividef(1.0f, 1.0f + __expf(-x));
}
__device__ __forceinline__ float tanhf_fast(float x){
    return 2.0f*sigf(2.0f*x) - 1.0f;
}
__device__ __forceinline__ float gru_c(float xr,float hr,float xz,float hz,
                                       float xn,float hn,float hold){
    float r = sigf(xr+hr);
    float z = sigf(xz+hz);
    float n = tanhf_fast(fmaf(r, hn, xn));
    return n + z*(hold - n);   // (1-z)*n + z*hold
}

__global__ __launch_bounds__(TB, 1)
void gru2_kernel(const float* __restrict__ x,
    const float* __restrict__ Wih0, const float* __restrict__ Whh0,
    const float* __restrict__ bih0, const float* __restrict__ bhh0,
    const float* __restrict__ Wih1, const float* __restrict__ Whh1,
    const float* __restrict__ bih1, const float* __restrict__ bhh1,
    const float* __restrict__ Wfc,  const float* __restrict__ bfc,
    float* __restrict__ out)
{
    // shared: x tile [t][i] -> 4 rows packed in float4; states k-major, 4 rows/float4
    __shared__ float4 x_sh[256*6];       // 24 KB
    __shared__ float4 h1b[2][64];        // layer-0 output, double buffered
    __shared__ float4 h2sh[64];          // layer-1 state
    __shared__ float4 g0x[192], g0h[192];// layer-0 gate pre-activations (x-part, h-part)
    __shared__ float4 g1x[192], g1h[192];// layer-1 gate pre-activations

    const int tid = threadIdx.x;
    const int b0  = blockIdx.x * BT;

    // ---- stage x tile: global coalesced read, shared [q][r] layout ----
    {
        float* xs = (float*)x_sh;
        for (int idx = tid; idx < BT*256*6; idx += TB){
            int r = idx / (256*6);
            int q = idx - r*(256*6);
            xs[q*4 + r] = x[(long)(b0+r)*(256*6) + q];
        }
    }
    if (tid < 64){
        h1b[1][tid] = make_float4(0.f,0.f,0.f,0.f);
        h2sh[tid]   = make_float4(0.f,0.f,0.f,0.f);
    }

    // ---- weight-stationary registers: one gate row per lane ----
    float w[64];
    float wx[6];
    float bias_m = 0.f, bias_x = 0.f;
    if (tid < 192){                       // layer 0: both W_hh0 row and W_ih0 row
        int g = tid;
        #pragma unroll
        for (int k=0;k<64;k++) w[k] = Whh0[g*64+k];
        #pragma unroll
        for (int i=0;i<6;i++)  wx[i] = Wih0[g*6+i];
        bias_m = bhh0[g];
        bias_x = bih0[g];
    } else if (tid < 384){                // layer 1: W_ih1 row
        int g = tid-192;
        #pragma unroll
        for (int k=0;k<64;k++) w[k] = Wih1[g*64+k];
        bias_m = bih1[g];
    } else {                              // layer 1: W_hh1 row
        int g = tid-384;
        #pragma unroll
        for (int k=0;k<64;k++) w[k] = Whh1[g*64+k];
        bias_m = bhh1[g];
    }
    __syncthreads();

    // ---- main loop: layer-0 at step t, layer-1 at step t-1 (pipelined) ----
    // Only barrier-0 (__syncthreads) is used: gate-compute phase, barrier,
    // activation phase, barrier. No named barriers.
    for (int t=0; t<=256; t++){
        const float4* h1p = h1b[(t+1)&1];     // h1[t-1] (zeros at t=0)
        bool act = (tid<192) ? (t<256) : (t>=1);
        if (act){
            // unified 64-length dot: src = h1_prev for layer0 & layer1-x, h2 for layer1-h
            const float4* src = (tid<384) ? h1p : h2sh;
            float a0=bias_m, a1=bias_m, a2=bias_m, a3=bias_m;
            #pragma unroll
            for (int k=0;k<64;k++){
                float4 hv = src[k];           // broadcast LDS.128
                a0 = fmaf(w[k], hv.x, a0);
                a1 = fmaf(w[k], hv.y, a1);
                a2 = fmaf(w[k], hv.z, a2);
                a3 = fmaf(w[k], hv.w, a3);
            }
            if (tid < 192){
                float c0=bias_x,c1=bias_x,c2=bias_x,c3=bias_x;
                const float4* xt = &x_sh[t*6];
                #pragma unroll
                for (int i=0;i<6;i++){
                    float4 v = xt[i];
                    c0 = fmaf(wx[i], v.x, c0);
                    c1 = fmaf(wx[i], v.y, c1);
                    c2 = fmaf(wx[i], v.z, c2);
                    c3 = fmaf(wx[i], v.w, c3);
                }
                g0x[tid] = make_float4(c0,c1,c2,c3);
                g0h[tid] = make_float4(a0,a1,a2,a3);
            } else if (tid < 384){
                g1x[tid-192] = make_float4(a0,a1,a2,a3);
            } else {
                g1h[tid-384] = make_float4(a0,a1,a2,a3);
            }
        }
        __syncthreads();
        // ---- activation phase ----
        if (tid < 64){
            if (t < 256){
                int j = tid;
                float4 xr=g0x[j],     hr=g0h[j];
                float4 xz=g0x[j+64],  hz=g0h[j+64];
                float4 xn=g0x[j+128], hn=g0h[j+128];
                float4 ho = h1p[j];
                float4 hv;
                hv.x = gru_c(xr.x,hr.x,xz.x,hz.x,xn.x,hn.x,ho.x);
                hv.y = gru_c(xr.y,hr.y,xz.y,hz.y,xn.y,hn.y,ho.y);
                hv.z = gru_c(xr.z,hr.z,xz.z,hz.z,xn.z,hn.z,ho.z);
                hv.w = gru_c(xr.w,hr.w,xz.w,hz.w,xn.w,hn.w,ho.w);
                h1b[t&1][j] = hv;
            }
        } else if (tid >= 192 && tid < 256){
            if (t >= 1){
                int j = tid - 192;
                float4 xr=g1x[j],     hr=g1h[j];
                float4 xz=g1x[j+64],  hz=g1h[j+64];
                float4 xn=g1x[j+128], hn=g1h[j+128];
                float4 ho = h2sh[j];
                float4 hv;
                hv.x = gru_c(xr.x,hr.x,xz.x,hz.x,xn.x,hn.x,ho.x);
                hv.y = gru_c(xr.y,hr.y,xz.y,hz.y,xn.y,hn.y,ho.y);
                hv.z = gru_c(xr.z,hr.z,xz.z,hz.z,xn.z,hn.z,ho.z);
                hv.w = gru_c(xr.w,hr.w,xz.w,hz.w,xn.w,hn.w,ho.w);
                h2sh[j] = hv;
            }
        }
        __syncthreads();
    }

    // ---- final FC: out[b] = h2[b] . W_fc + b_fc ----
    if (tid < BT){
        float s = bfc[0];
        const float* h2f = (const float*)h2sh;
        #pragma unroll
        for (int j=0;j<64;j++)
            s += h2f[j*4 + tid] * Wfc[j];
        out[b0 + tid] = s;
    }
}

extern "C" void kernel_launch(void* const* d_in, const int* in_sizes, int n_in,
                              void* d_out, int out_size)
{
    (void)in_sizes; (void)n_in; (void)out_size;
    gru2_kernel<<<4096/BT, TB>>>(
        (const float*)d_in[0],
        (const float*)d_in[1], (const float*)d_in[2],
        (const float*)d_in[3], (const float*)d_in[4],
        (const float*)d_in[5], (const float*)d_in[6],
        (const float*)d_in[7], (const float*)d_in[8],
        (const float*)d_in[9], (const float*)d_in[10],
        (float*)d_out);
}

// round 4
// speedup vs baseline: 1.0578x; 1.0578x over previous
#include <cuda_runtime.h>
#include <cstdint>

#define TB 320
#define BT 4

__device__ __forceinline__ void ffma2(unsigned long long &acc,
                                      unsigned long long a,
                                      unsigned long long b){
    asm("fma.rn.f32x2 %0, %1, %2, %0;" : "+l"(acc) : "l"(a), "l"(b));
}
__device__ __forceinline__ float psum(unsigned long long a){
    float lo = __uint_as_float((unsigned int)a);
    float hi = __uint_as_float((unsigned int)(a >> 32));
    return lo + hi;
}
__device__ __forceinline__ unsigned long long packb(float b){
    return (unsigned long long)__float_as_uint(b);   // {b, +0.0f}
}
__device__ __forceinline__ float sigf(float x){
    return __fdividef(1.0f, 1.0f + __expf(-x));
}
__device__ __forceinline__ float tanhf_fast(float x){
    return 2.0f*sigf(2.0f*x) - 1.0f;
}

__global__ __launch_bounds__(TB, 1)
void gru2_kernel(const float* __restrict__ x,
    const float* __restrict__ Wih0, const float* __restrict__ Whh0,
    const float* __restrict__ bih0, const float* __restrict__ bhh0,
    const float* __restrict__ Wih1, const float* __restrict__ Whh1,
    const float* __restrict__ bih1, const float* __restrict__ bhh1,
    const float* __restrict__ Wfc,  const float* __restrict__ bfc,
    float* __restrict__ out)
{
    __shared__ float4 x_sh[256*6];            // 24 KB  [t*6+i] = x over 4 batch elems
    __shared__ float4 gA[192];                // layer0 x-part  (b_ih0 folded)
    __shared__ float4 gB[192];                // layer0 h-part  (b_hh0 folded)
    __shared__ float4 gC[192];                // layer1 ih-part (b_ih1 folded)
    __shared__ float4 gD[192];                // layer1 hh-part (b_hh1 folded)
    __shared__ float  h1T[2][4][64];          // transposed h1, double buffered
    __shared__ float  h2T[4][64];             // transposed h2

    const int tid = threadIdx.x;
    const int b0  = blockIdx.x * BT;

    // ---- stage x tile ----
    {
        float* xs = (float*)x_sh;
        for (int idx = tid; idx < BT*256*6; idx += TB){
            int r = idx / (256*6);
            int q = idx - r*(256*6);
            xs[q*4 + r] = x[(long)(b0+r)*(256*6) + q];
        }
    }
    if (tid < 256){
        ((float*)h1T[1])[tid] = 0.f;
        ((float*)h2T)[tid]    = 0.f;
    }

    // ---- weight-stationary registers: TWO gate rows per lane, k-pair packed ----
    const int l = tid;
    unsigned long long w0[32], w1[32];
    float wx0[6], wx1[6];
    unsigned long long b2_0 = 0, b2_1 = 0;
    float bx0 = 0.f, bx1 = 0.f;

    if (l < 288){
        int r0 = 2*l;
        const float* M; int g;
        if (l < 96){
            M = Whh0; g = r0;
            b2_0 = packb(bhh0[g]); b2_1 = packb(bhh0[g+1]);
            bx0 = bih0[g]; bx1 = bih0[g+1];
            #pragma unroll
            for (int i=0;i<6;i++){ wx0[i] = Wih0[g*6+i]; wx1[i] = Wih0[(g+1)*6+i]; }
        } else if (l < 192){
            M = Wih1; g = r0 - 192;
            b2_0 = packb(bih1[g]); b2_1 = packb(bih1[g+1]);
        } else {
            M = Whh1; g = r0 - 384;
            b2_0 = packb(bhh1[g]); b2_1 = packb(bhh1[g+1]);
        }
        const unsigned long long* Wr0 = (const unsigned long long*)(M + g*64);
        const unsigned long long* Wr1 = (const unsigned long long*)(M + (g+1)*64);
        #pragma unroll
        for (int q=0;q<32;q++){ w0[q] = Wr0[q]; w1[q] = Wr1[q]; }
    }
    __syncthreads();

    // ---- main loop: layer-0 at step t, layer-1 at step t-1 (pipelined) ----
    for (int t=0; t<=256; t++){
        const int prev = (t+1)&1;
        const int cur  = t&1;

        // === gate phase ===
        bool act = (l < 96) ? (t < 256) : (l < 288 && t >= 1);
        if (act){
            const float* src = (l < 192) ? &h1T[prev][0][0] : &h2T[0][0];
            const ulonglong2* s0 = (const ulonglong2*)(src);
            const ulonglong2* s1 = (const ulonglong2*)(src + 64);
            const ulonglong2* s2 = (const ulonglong2*)(src + 128);
            const ulonglong2* s3 = (const ulonglong2*)(src + 192);

            unsigned long long a0[4], a1[4];
            #pragma unroll
            for (int e=0;e<4;e++){ a0[e] = b2_0; a1[e] = b2_1; }

            #pragma unroll
            for (int q=0;q<16;q++){
                ulonglong2 p0 = s0[q];
                ffma2(a0[0], w0[2*q], p0.x); ffma2(a0[0], w0[2*q+1], p0.y);
                ffma2(a1[0], w1[2*q], p0.x); ffma2(a1[0], w1[2*q+1], p0.y);
                ulonglong2 p1 = s1[q];
                ffma2(a0[1], w0[2*q], p1.x); ffma2(a0[1], w0[2*q+1], p1.y);
                ffma2(a1[1], w1[2*q], p1.x); ffma2(a1[1], w1[2*q+1], p1.y);
                ulonglong2 p2 = s2[q];
                ffma2(a0[2], w0[2*q], p2.x); ffma2(a0[2], w0[2*q+1], p2.y);
                ffma2(a1[2], w1[2*q], p2.x); ffma2(a1[2], w1[2*q+1], p2.y);
                ulonglong2 p3 = s3[q];
                ffma2(a0[3], w0[2*q], p3.x); ffma2(a0[3], w0[2*q+1], p3.y);
                ffma2(a1[3], w1[2*q], p3.x); ffma2(a1[3], w1[2*q+1], p3.y);
            }

            float4 r0v = make_float4(psum(a0[0]), psum(a0[1]), psum(a0[2]), psum(a0[3]));
            float4 r1v = make_float4(psum(a1[0]), psum(a1[1]), psum(a1[2]), psum(a1[3]));
            int r0 = 2*l;
            if (l < 96){
                gB[r0] = r0v; gB[r0+1] = r1v;
                // x-part (6-dot)
                float c00=bx0,c01=bx0,c02=bx0,c03=bx0;
                float c10=bx1,c11=bx1,c12=bx1,c13=bx1;
                const float4* xt = &x_sh[t*6];
                #pragma unroll
                for (int i=0;i<6;i++){
                    float4 v = xt[i];
                    c00 = fmaf(wx0[i], v.x, c00); c01 = fmaf(wx0[i], v.y, c01);
                    c02 = fmaf(wx0[i], v.z, c02); c03 = fmaf(wx0[i], v.w, c03);
                    c10 = fmaf(wx1[i], v.x, c10); c11 = fmaf(wx1[i], v.y, c11);
                    c12 = fmaf(wx1[i], v.z, c12); c13 = fmaf(wx1[i], v.w, c13);
                }
                gA[r0]   = make_float4(c00,c01,c02,c03);
                gA[r0+1] = make_float4(c10,c11,c12,c13);
            } else if (l < 192){
                gC[r0-192] = r0v; gC[r0-191] = r1v;
            } else {
                gD[r0-384] = r0v; gD[r0-383] = r1v;
            }
        }
        __syncthreads();

        // === activation phase: 256 lanes, one (j, e) each, both layers ===
        if (tid < 256){
            int j = tid >> 2, e = tid & 3;
            const float* gAf = (const float*)gA;
            const float* gBf = (const float*)gB;
            const float* gCf = (const float*)gC;
            const float* gDf = (const float*)gD;
            if (t < 256){
                float xr = gAf[ j     *4+e], hr = gBf[ j     *4+e];
                float xz = gAf[(j+64) *4+e], hz = gBf[(j+64) *4+e];
                float xn = gAf[(j+128)*4+e], hn = gBf[(j+128)*4+e];
                float hold = h1T[prev][e][j];
                float r = sigf(xr+hr);
                float z = sigf(xz+hz);
                float n = tanhf_fast(fmaf(r, hn, xn));
                h1T[cur][e][j] = n + z*(hold - n);
            }
            if (t >= 1){
                float xr = gCf[ j     *4+e], hr = gDf[ j     *4+e];
                float xz = gCf[(j+64) *4+e], hz = gDf[(j+64) *4+e];
                float xn = gCf[(j+128)*4+e], hn = gDf[(j+128)*4+e];
                float hold = h2T[e][j];
                float r = sigf(xr+hr);
                float z = sigf(xz+hz);
                float n = tanhf_fast(fmaf(r, hn, xn));
                h2T[e][j] = n + z*(hold - n);
            }
        }
        __syncthreads();
    }

    // ---- final FC ----
    if (tid < BT){
        float s = bfc[0];
        #pragma unroll
        for (int j=0;j<64;j++)
            s = fmaf(h2T[tid][j], Wfc[j], s);
        out[b0 + tid] = s;
    }
}

extern "C" void kernel_launch(void* const* d_in, const int* in_sizes, int n_in,
                              void* d_out, int out_size)
{
    (void)in_sizes; (void)n_in; (void)out_size;
    gru2_kernel<<<4096/BT, TB>>>(
        (const float*)d_in[0],
        (const float*)d_in[1], (const float*)d_in[2],
        (const float*)d_in[3], (const float*)d_in[4],
        (const float*)d_in[5], (const float*)d_in[6],
        (const float*)d_in[7], (const float*)d_in[8],
        (const float*)d_in[9], (const float*)d_in[10],
        (float*)d_out);
}